// round 2
// baseline (speedup 1.0000x reference)
#include <cuda_runtime.h>
#include <stdint.h>

#define Bq 4
#define Tq 2048
#define Dq 1024
#define Hq 16
#define Sq 64
#define Cq 64
#define NTq (Bq*Tq)      // 8192 rows
#define NCq (Tq/Cq)      // 32 chunks
#define BHq (Bq*Hq)      // 64 (b,h) pairs

// ---------------- scratch (static __device__, allocation-free) ----------------
__device__ int8_t g_Wq[5][Dq*Dq];          // ternary weights as int8
__device__ float  g_wpart[5][64];
__device__ float  g_wscale[5];
__device__ int8_t g_Xq[5][NTq*Dq];         // quantized activations
__device__ float  g_xscale[5][NTq];
__device__ float  g_Y[4][NTq*Dq];          // r,k,v,g projection outputs (fp32)
__device__ float  g_states[BHq*NCq*Sq*Sq]; // per-chunk contributions -> states
__device__ float  g_ywkv[NTq*Dq];          // wkv output in (B,T,D)

// ---------------- compensated reduction helpers (TwoSum / double-float) ------
// combine two (hi,lo) partial sums; error-free at fp32 speed
__device__ __forceinline__ float2 df_comb(float2 a, float2 b){
  float s  = a.x + b.x;
  float bp = s - a.x;
  float er = (a.x - (s - bp)) + (b.x - bp);
  return make_float2(s, a.y + b.y + er);
}

// block-wide compensated sum of per-thread float partials; returns exact-ish sum
__device__ __forceinline__ float block_reduce256(float v, float2* sb, int tid){
  __syncthreads();            // guard WAR on sb from previous use
  sb[tid]=make_float2(v,0.f);
  __syncthreads();
  #pragma unroll
  for(int s=128;s>0;s>>=1){
    if(tid<s) sb[tid]=df_comb(sb[tid],sb[tid+s]);
    __syncthreads();
  }
  float2 r=sb[0];
  return r.x + r.y;
}

// accurate rsqrt(x + eps) via fp64 (cheap: once per row/group)
__device__ __forceinline__ float inv_sqrt_eps(float var, float eps){
  float ve = __fadd_rn(var, eps);
  return (float)(1.0 / sqrt((double)ve));
}

// exp(n * lw) with exact hi/lo argument split: expf(hi)*(1+lo)
__device__ __forceinline__ float exp_nlw(float n, float lw){
  float hi = __fmul_rn(n, lw);
  float lo = __fmaf_rn(n, lw, -hi);
  return __fmul_rn(expf(hi), __fadd_rn(1.f, lo));
}

// LayerNorm (two-pass) + abs-mean + int8 quantize of a shared-memory row.
__device__ void ln_quant(const float* arr, const float* g, const float* b,
                         int j, int bt, float2* red, int tid){
  float s=0.f;
  for(int d=tid; d<Dq; d+=256) s+=arr[d];
  float m = __fmul_rn(block_reduce256(s,red,tid), 1.f/Dq);
  float s2=0.f;
  for(int d=tid; d<Dq; d+=256){ float v=__fsub_rn(arr[d],m); s2=__fadd_rn(s2,__fmul_rn(v,v)); }
  float var = __fmul_rn(block_reduce256(s2,red,tid), 1.f/Dq);
  float inv = inv_sqrt_eps(var, 1e-5f);
  float sa=0.f;
  for(int d=tid; d<Dq; d+=256){
    float v=__fadd_rn(__fmul_rn(__fmul_rn(__fsub_rn(arr[d],m),inv),g[d]),b[d]);
    sa=__fadd_rn(sa,fabsf(v));
  }
  float am = __fmul_rn(block_reduce256(sa,red,tid), 1.f/Dq);
  float clipv = __fmul_rn(fmaxf(am,1e-8f), 2.5f);
  float scale = __fdiv_rn(clipv, 127.f);
  for(int d=tid; d<Dq; d+=256){
    float v=__fadd_rn(__fmul_rn(__fmul_rn(__fsub_rn(arr[d],m),inv),g[d]),b[d]);
    float xs=__fdiv_rn(v,scale);
    float q = rintf(fminf(fmaxf(xs,-127.f),127.f));
    g_Xq[j][bt*Dq+d]=(int8_t)q;
  }
  if(tid==0) g_xscale[j][bt]=scale;
}

// ---------------- weight quantization ----------------
__global__ void wq_part(const float* __restrict__ pw){
  // grid (64, 5), block 256
  int j=blockIdx.y, sl=blockIdx.x, tid=threadIdx.x;
  __shared__ float2 red[256];
  const float* w = pw + j*(Dq*Dq) + sl*16384;
  float s=0.f;
  for(int i=tid;i<16384;i+=256) s+=fabsf(w[i]);
  float tot=block_reduce256(s,red,tid);
  if(tid==0) g_wpart[j][sl]=tot;
}

__global__ void wq_final(){
  int tid=threadIdx.x;
  if(tid<5){
    double s=0.0;
    for(int i=0;i<64;i++) s+=(double)g_wpart[tid][i];
    g_wscale[tid]=fmaxf((float)(s*(1.0/(double)(Dq*Dq))),1e-8f);
  }
}

__global__ void wq_quant(const float* __restrict__ pw){
  // grid 5120, block 256; 4 elems/thread (one weight matrix = 1024 blocks)
  int gi = blockIdx.x*1024 + threadIdx.x*4;
  int j  = gi >> 20;
  float sc = g_wscale[j];
  float4 wv = *(const float4*)&pw[gi];
  char4 q;
  q.x=(int8_t)rintf(fminf(fmaxf(__fdiv_rn(wv.x,sc),-1.f),1.f));
  q.y=(int8_t)rintf(fminf(fmaxf(__fdiv_rn(wv.y,sc),-1.f),1.f));
  q.z=(int8_t)rintf(fminf(fmaxf(__fdiv_rn(wv.z,sc),-1.f),1.f));
  q.w=(int8_t)rintf(fminf(fmaxf(__fdiv_rn(wv.w,sc),-1.f),1.f));
  *(char4*)&(((int8_t*)g_Wq)[gi]) = q;
}

// ---------------- token shift + 4x (LN + act quant) ----------------
__global__ void prep_rkvg(const float* __restrict__ x,
                          const float* __restrict__ mu_r, const float* __restrict__ mu_k,
                          const float* __restrict__ mu_v, const float* __restrict__ mu_g,
                          const float* __restrict__ ln_g, const float* __restrict__ ln_b){
  int bt = blockIdx.x;
  int t  = bt & (Tq-1);
  int tid= threadIdx.x;
  __shared__ float xr[Dq], xxr[Dq], nrm[Dq];
  __shared__ float2 red[256];
  for(int d=tid; d<Dq; d+=256){
    float xv = x[bt*Dq+d];
    float xp = (t==0)?0.f : x[(bt-1)*Dq+d];
    xr[d]=xv; xxr[d]=__fsub_rn(xp,xv);
  }
  const float* mus[4]={mu_r,mu_k,mu_v,mu_g};
  for(int j=0;j<4;j++){
    const float* mu=mus[j];
    __syncthreads();
    for(int d=tid; d<Dq; d+=256) nrm[d]=__fadd_rn(xr[d],__fmul_rn(xxr[d],mu[d]));
    ln_quant(nrm, ln_g+j*Dq, ln_b+j*Dq, j, bt, red, tid);
  }
}

// ---------------- int8 dp4a GEMM: C[M,N] = (Xq[j] . Wq[j]^T) * scales ----------------
#define GBM 128
#define GBN 128
#define GBKI 16   // 16 ints = 64 K-bytes per tile
__global__ void __launch_bounds__(256) gemm_i8(int j, float* __restrict__ dout){
  __shared__ int As[GBKI][GBM];
  __shared__ int Bs[GBKI][GBN];
  const int* A4 = (const int*)g_Xq[j];
  const int* B4 = (const int*)g_Wq[j];
  float* Cout = (j==4)? dout : g_Y[j];
  const int KI = Dq/4;   // 256 ints
  int m0 = blockIdx.y*GBM, n0 = blockIdx.x*GBN;
  int tid = threadIdx.x;
  int acc[8][8] = {};
  int tm = (tid>>4)*8, tn = (tid&15)*8;
  for(int kt=0; kt<KI; kt+=GBKI){
    #pragma unroll
    for(int l=0;l<2;l++){
      int idx = tid + l*256;   // 0..511 int4 slots
      int row = idx>>2, c4 = idx&3;
      int4 v = *(const int4*)&A4[(m0+row)*KI + kt + c4*4];
      As[c4*4+0][row]=v.x; As[c4*4+1][row]=v.y; As[c4*4+2][row]=v.z; As[c4*4+3][row]=v.w;
    }
    #pragma unroll
    for(int l=0;l<2;l++){
      int idx = tid + l*256;
      int row = idx>>2, c4 = idx&3;
      int4 v = *(const int4*)&B4[(n0+row)*KI + kt + c4*4];
      Bs[c4*4+0][row]=v.x; Bs[c4*4+1][row]=v.y; Bs[c4*4+2][row]=v.z; Bs[c4*4+3][row]=v.w;
    }
    __syncthreads();
    #pragma unroll
    for(int kk=0;kk<GBKI;kk++){
      int a[8], b[8];
      *(int4*)&a[0]=*(const int4*)&As[kk][tm];
      *(int4*)&a[4]=*(const int4*)&As[kk][tm+4];
      *(int4*)&b[0]=*(const int4*)&Bs[kk][tn];
      *(int4*)&b[4]=*(const int4*)&Bs[kk][tn+4];
      #pragma unroll
      for(int i=0;i<8;i++)
        #pragma unroll
        for(int jj=0;jj<8;jj++)
          acc[i][jj]=__dp4a(a[i],b[jj],acc[i][jj]);
    }
    __syncthreads();
  }
  float ws = g_wscale[j];
  #pragma unroll
  for(int i=0;i<8;i++){
    float sc = g_xscale[j][m0+tm+i]*ws;
    #pragma unroll
    for(int jj=0;jj<8;jj++)
      Cout[(m0+tm+i)*Dq + n0+tn+jj] = (float)acc[i][jj]*sc;
  }
}

// ---------------- WKV phase A: per-chunk contribution G_c = (K .* w^{C-1-t})^T @ V ----------------
__global__ void wkv_contrib(const float* __restrict__ ld_in){
  int c = blockIdx.x, bh = blockIdx.y;
  int b = bh>>4, h = bh&15;
  int tid = threadIdx.x;
  __shared__ float kw[Cq*Sq], vs[Cq*Sq], lws[Sq];
  if(tid<Sq){
    float w = expf(-expf(ld_in[h*Sq+tid]));
    lws[tid] = logf(fmaxf(w,1e-38f));
  }
  __syncthreads();
  const float* Yk = g_Y[1];
  const float* Yv = g_Y[2];
  int base = (b*Tq + c*Cq)*Dq + h*Sq;
  for(int idx=tid; idx<Cq*Sq; idx+=256){
    int t=idx>>6, s=idx&63;
    kw[idx] = __fmul_rn(Yk[base + t*Dq + s], exp_nlw((float)(Cq-1-t), lws[s]));
    vs[idx] = Yv[base + t*Dq + s];
  }
  __syncthreads();
  int ts=(tid>>4)*4, to=(tid&15)*4;
  float acc[4][4]={};
  for(int t=0;t<Cq;t++){
    float4 a=*(const float4*)&kw[t*Sq+ts];
    float4 v=*(const float4*)&vs[t*Sq+to];
    acc[0][0]+=a.x*v.x; acc[0][1]+=a.x*v.y; acc[0][2]+=a.x*v.z; acc[0][3]+=a.x*v.w;
    acc[1][0]+=a.y*v.x; acc[1][1]+=a.y*v.y; acc[1][2]+=a.y*v.z; acc[1][3]+=a.y*v.w;
    acc[2][0]+=a.z*v.x; acc[2][1]+=a.z*v.y; acc[2][2]+=a.z*v.z; acc[2][3]+=a.z*v.w;
    acc[3][0]+=a.w*v.x; acc[3][1]+=a.w*v.y; acc[3][2]+=a.w*v.z; acc[3][3]+=a.w*v.w;
  }
  float* G = &g_states[(bh*NCq + c)*Sq*Sq];
  #pragma unroll
  for(int i=0;i<4;i++)
    #pragma unroll
    for(int jj=0;jj<4;jj++)
      G[(ts+i)*Sq + to+jj]=acc[i][jj];
}

// ---------------- WKV phase B: scan  state_{c+1} = w^C*state_c + G_c (in-place) ----------------
__global__ void wkv_scan(const float* __restrict__ ld_in){
  int bh = blockIdx.x, h = bh&15;
  int tid = threadIdx.x;
  __shared__ float wC[Sq];
  if(tid<Sq){
    float w = expf(-expf(ld_in[h*Sq+tid]));
    float lw = logf(fmaxf(w,1e-38f));
    wC[tid] = expf(__fmul_rn((float)Cq,lw));   // 64*lw exact (pow2 mult)
  }
  __syncthreads();
  for(int e=tid; e<Sq*Sq; e+=256){
    float wc = wC[e>>6];
    float cur = 0.f;
    float* Gp = &g_states[bh*NCq*Sq*Sq + e];
    for(int c=0;c<NCq;c++){
      float gv = Gp[c*Sq*Sq];
      Gp[c*Sq*Sq]=cur;           // now holds state BEFORE chunk c
      cur = __fadd_rn(__fmul_rn(wc,cur), gv);  // match ref mul-then-add
    }
  }
}

// ---------------- WKV phase C: per-chunk output ----------------
__global__ void __launch_bounds__(256) wkv_main(const float* __restrict__ ld_in,
                                                const float* __restrict__ u_in){
  extern __shared__ float sm[];
  float* rpT = sm;               // [S][C] : r * w^{-t}
  float* rwT = sm + 4096;        // [S][C] : r * w^{t+1}
  float* kpT = sm + 8192;        // [S][C] : k * w^{t}
  float* vs  = sm + 12288;       // [C][S]
  float* st  = sm + 16384;       // [S][S] state before chunk
  float* PT  = sm + 20480;       // [C(i)][C(t)] masked
  __shared__ float lws[Sq], uex[Sq], dv[Cq];

  int c = blockIdx.x, bh = blockIdx.y;
  int b = bh>>4, h = bh&15;
  int tid = threadIdx.x;
  if(tid<Sq){
    float w = expf(-expf(ld_in[h*Sq+tid]));
    lws[tid]=logf(fmaxf(w,1e-38f));
    uex[tid]=expf(u_in[h*Sq+tid]);
  }
  __syncthreads();
  const float* Yr=g_Y[0]; const float* Yk=g_Y[1]; const float* Yv=g_Y[2];
  int base = (b*Tq + c*Cq)*Dq + h*Sq;
  const float* Gst = &g_states[(bh*NCq + c)*Sq*Sq];
  for(int idx=tid; idx<Cq*Sq; idx+=256){
    int t=idx>>6, s=idx&63;
    float rv=Yr[base + t*Dq + s];
    float kv=Yk[base + t*Dq + s];
    float vv=Yv[base + t*Dq + s];
    float lw=lws[s];
    float ekt=exp_nlw((float)t, lw);        // w^t
    float ein=exp_nlw(-(float)t, lw);       // w^-t
    rpT[s*Cq+t]=__fmul_rn(rv,ein);
    rwT[s*Cq+t]=__fmul_rn(rv,exp_nlw((float)(t+1), lw)); // r*w^{t+1}
    kpT[s*Cq+t]=__fmul_rn(kv,ekt);
    vs[t*Sq+s]=vv;
    st[idx]=Gst[idx];
  }
  __syncthreads();
  // bonus diag: d[t] = sum_s r*u_exp*k  (recover r*k = rpT*kpT; e^{-t}e^{t}=1±1ulp)
  if(tid<Cq){
    float a=0.f;
    for(int s=0;s<Sq;s++) a += rpT[s*Cq+tid]*kpT[s*Cq+tid]*uex[s];
    dv[tid]=a;
  }
  __syncthreads();
  // P[t][i] = (i>=t) * sum_s rpT[s][t]*kpT[s][i]; store transposed PT[i][t]
  int tt=(tid>>4)*4, ti=(tid&15)*4;
  {
    float acc[4][4]={};
    for(int s=0;s<Sq;s++){
      float4 a=*(const float4*)&rpT[s*Cq+tt];
      float4 k4=*(const float4*)&kpT[s*Cq+ti];
      acc[0][0]+=a.x*k4.x; acc[0][1]+=a.x*k4.y; acc[0][2]+=a.x*k4.z; acc[0][3]+=a.x*k4.w;
      acc[1][0]+=a.y*k4.x; acc[1][1]+=a.y*k4.y; acc[1][2]+=a.y*k4.z; acc[1][3]+=a.y*k4.w;
      acc[2][0]+=a.z*k4.x; acc[2][1]+=a.z*k4.y; acc[2][2]+=a.z*k4.z; acc[2][3]+=a.z*k4.w;
      acc[3][0]+=a.w*k4.x; acc[3][1]+=a.w*k4.y; acc[3][2]+=a.w*k4.z; acc[3][3]+=a.w*k4.w;
    }
    #pragma unroll
    for(int i=0;i<4;i++)
      #pragma unroll
      for(int jj=0;jj<4;jj++)
        PT[(ti+jj)*Cq + (tt+i)] = (ti+jj >= tt+i) ? acc[i][jj] : 0.f;
  }
  __syncthreads();
  // y[t][o] = sum_i PT[i][t]*v[i][o] + sum_s rwT[s][t]*st[s][o] + d[t]*v[t][o]
  int to = ti;
  {
    float acc[4][4]={};
    for(int l=0;l<Sq;l++){
      float4 a =*(const float4*)&PT[l*Cq+tt];
      float4 v4=*(const float4*)&vs[l*Sq+to];
      float4 r4=*(const float4*)&rwT[l*Cq+tt];
      float4 s4=*(const float4*)&st[l*Sq+to];
      acc[0][0]+=a.x*v4.x+r4.x*s4.x; acc[0][1]+=a.x*v4.y+r4.x*s4.y;
      acc[0][2]+=a.x*v4.z+r4.x*s4.z; acc[0][3]+=a.x*v4.w+r4.x*s4.w;
      acc[1][0]+=a.y*v4.x+r4.y*s4.x; acc[1][1]+=a.y*v4.y+r4.y*s4.y;
      acc[1][2]+=a.y*v4.z+r4.y*s4.z; acc[1][3]+=a.y*v4.w+r4.y*s4.w;
      acc[2][0]+=a.z*v4.x+r4.z*s4.x; acc[2][1]+=a.z*v4.y+r4.z*s4.y;
      acc[2][2]+=a.z*v4.z+r4.z*s4.z; acc[2][3]+=a.z*v4.w+r4.z*s4.w;
      acc[3][0]+=a.w*v4.x+r4.w*s4.x; acc[3][1]+=a.w*v4.y+r4.w*s4.y;
      acc[3][2]+=a.w*v4.z+r4.w*s4.z; acc[3][3]+=a.w*v4.w+r4.w*s4.w;
    }
    #pragma unroll
    for(int i=0;i<4;i++){
      float dd = dv[tt+i];
      #pragma unroll
      for(int jj=0;jj<4;jj++){
        float y = __fadd_rn(acc[i][jj], __fmul_rn(dd,vs[(tt+i)*Sq + to+jj]));
        g_ywkv[(b*Tq + c*Cq + tt+i)*Dq + h*Sq + to+jj] = y;
      }
    }
  }
}

// ---------------- GroupNorm + SiLU gate + LN + quant (feeds final projection) ----------------
__global__ void gate_prep(const float* __restrict__ gn_g, const float* __restrict__ gn_b,
                          const float* __restrict__ ln_g, const float* __restrict__ ln_b){
  int bt=blockIdx.x, tid=threadIdx.x;
  __shared__ float yr[Dq], gated[Dq], gm[Hq], gi[Hq];
  __shared__ float2 red[256];
  for(int d=tid; d<Dq; d+=256) yr[d]=g_ywkv[bt*Dq+d];
  __syncthreads();
  int w=tid>>5, lane=tid&31;
  for(int gg=2*w; gg<2*w+2; gg++){
    float e1=yr[gg*Sq+lane], e2=yr[gg*Sq+32+lane];
    // compensated warp sum
    float2 s = df_comb(make_float2(e1,0.f), make_float2(e2,0.f));
    #pragma unroll
    for(int o=16;o;o>>=1){
      float2 t2 = make_float2(__shfl_xor_sync(0xffffffffu,s.x,o),
                              __shfl_xor_sync(0xffffffffu,s.y,o));
      s = df_comb(s,t2);
    }
    float m=__fmul_rn(s.x+s.y, 1.f/Sq);
    float d1=__fsub_rn(e1,m), d2=__fsub_rn(e2,m);
    float2 s2 = df_comb(make_float2(__fmul_rn(d1,d1),0.f), make_float2(__fmul_rn(d2,d2),0.f));
    #pragma unroll
    for(int o=16;o;o>>=1){
      float2 t2 = make_float2(__shfl_xor_sync(0xffffffffu,s2.x,o),
                              __shfl_xor_sync(0xffffffffu,s2.y,o));
      s2 = df_comb(s2,t2);
    }
    if(lane==0){
      gm[gg]=m;
      gi[gg]=inv_sqrt_eps(__fmul_rn(s2.x+s2.y, 1.f/Sq), 1e-5f);
    }
  }
  __syncthreads();
  for(int d=tid; d<Dq; d+=256){
    int gg=d>>6;
    float yn=__fadd_rn(__fmul_rn(__fmul_rn(__fsub_rn(yr[d],gm[gg]),gi[gg]),gn_g[d]),gn_b[d]);
    float gv=g_Y[3][bt*Dq+d];
    float sig=__fdiv_rn(1.f, __fadd_rn(1.f, expf(-gv)));
    float sil=__fmul_rn(gv,sig);
    gated[d]=__fmul_rn(yn,sil);
  }
  ln_quant(gated, ln_g+4*Dq, ln_b+4*Dq, 4, bt, red, tid);
}

// ---------------- launch ----------------
extern "C" void kernel_launch(void* const* d_in, const int* in_sizes, int n_in,
                              void* d_out, int out_size){
  const float* x        =(const float*)d_in[0];
  const float* mu_r     =(const float*)d_in[1];
  const float* mu_k     =(const float*)d_in[2];
  const float* mu_v     =(const float*)d_in[3];
  const float* mu_g     =(const float*)d_in[4];
  const float* log_decay=(const float*)d_in[5];
  const float* u        =(const float*)d_in[6];
  const float* proj_w   =(const float*)d_in[7];
  const float* ln_g     =(const float*)d_in[8];
  const float* ln_b     =(const float*)d_in[9];
  const float* gn_g     =(const float*)d_in[10];
  const float* gn_b     =(const float*)d_in[11];
  float* out=(float*)d_out;

  cudaFuncSetAttribute(wkv_main, cudaFuncAttributeMaxDynamicSharedMemorySize, 98304);

  // weight quantization (deterministic tree reduction)
  wq_part <<<dim3(64,5),256>>>(proj_w);
  wq_final<<<1,32>>>();
  wq_quant<<<5120,256>>>(proj_w);

  // token shift + LN + act quant for r,k,v,g
  prep_rkvg<<<NTq,256>>>(x,mu_r,mu_k,mu_v,mu_g,ln_g,ln_b);

  // 4 projection GEMMs (int8 dp4a)
  for(int j=0;j<4;j++)
    gemm_i8<<<dim3(Dq/GBN, NTq/GBM),256>>>(j,out);

  // WKV
  wkv_contrib<<<dim3(NCq,BHq),256>>>(log_decay);
  wkv_scan   <<<BHq,256>>>(log_decay);
  wkv_main   <<<dim3(NCq,BHq),256,98304>>>(log_decay,u);

  // GroupNorm + gate + final LN/quant
  gate_prep<<<NTq,256>>>(gn_g,gn_b,ln_g,ln_b);

  // output projection GEMM -> d_out
  gemm_i8<<<dim3(Dq/GBN, NTq/GBM),256>>>(4,out);
}